// round 7
// baseline (speedup 1.0000x reference)
#include <cuda_runtime.h>
#include <math_constants.h>

#define BB 8
#define NN 4096
#define KNN 20
#define EPSV 1e-5f
#define SLOPE 0.2f
#define NTOT ((float)(BB*NN*KNN))
#define PTS 32

typedef unsigned long long ull;

__device__ __forceinline__ void fma2(ull& d, ull a, ull b) {
    asm("fma.rn.f32x2 %0, %1, %2, %0;" : "+l"(d) : "l"(a), "l"(b));
}
__device__ __forceinline__ ull add2(ull a, ull b) {
    ull r; asm("add.rn.f32x2 %0, %1, %2;" : "=l"(r) : "l"(a), "l"(b)); return r;
}
__device__ __forceinline__ ull pack2(float lo, float hi) {
    ull r; asm("mov.b64 %0, {%1, %2};" : "=l"(r) : "f"(lo), "f"(hi)); return r;
}
__device__ __forceinline__ void unpack2(ull v, float& lo, float& hi) {
    asm("mov.b64 {%0, %1}, %2;" : "=f"(lo), "=f"(hi) : "l"(v));
}
__device__ __forceinline__ void cp4(unsigned dst, const float* src) {
    asm volatile("cp.async.ca.shared.global [%0], [%1], 4;" :: "r"(dst), "l"(src));
}

__device__ int   g_idx[BB*NN*KNN];
__device__ float g_mom[27];
__device__ float g_scale1[64], g_shift1[64];
__device__ float g_sum2[64], g_sumsq2[64];
__device__ float g_scale2[64], g_shift2[64];
__device__ float g_maxb[BB*NN*64];
__device__ float g_minb[BB*NN*64];

__global__ void zero_kernel() {
    int t = threadIdx.x;
    if (t < 27) g_mom[t] = 0.f;
    if (t < 64) { g_sum2[t] = 0.f; g_sumsq2[t] = 0.f; }
}

// Branchless PARALLEL insertion (depth ~2).
__device__ __forceinline__ void insert20(float (&dl)[KNN], int (&il)[KNN],
                                         float dd, int m) {
#pragma unroll
    for (int j = KNN - 1; j >= 1; j--) {
        bool b1 = dd < dl[j - 1];
        bool b2 = dd < dl[j];
        dl[j] = b1 ? dl[j - 1] : (b2 ? dd : dl[j]);
        il[j] = b1 ? il[j - 1] : (b2 ? m  : il[j]);
    }
    bool b0 = dd < dl[0];
    dl[0] = b0 ? dd : dl[0];
    il[0] = b0 ? m  : il[0];
}

// KNN: 32 queries/block, 4 m-partitions of 1024, WARP = PARTITION so the
// candidate-drain vote stays warp-coherent (R4's failure was voteless
// per-lane drains). Partition lists merged in ascending-partition order
// with strict '<' => identical selection/ties to a serial ascending-m scan.
__global__ __launch_bounds__(128) void knn_kernel(const float* __restrict__ x) {
    __shared__ float sx[NN], sy[NN], sz[NN];
    __shared__ unsigned short sbuf[32][128];
    __shared__ float mdist[KNN][96];
    __shared__ unsigned short midx[KNN][96];
    int b = blockIdx.y;
    int t = threadIdx.x;
    const float* xb = x + b * 3 * NN;
    for (int i = t; i < NN; i += 128) {
        sx[i] = xb[i];
        sy[i] = xb[NN + i];
        sz[i] = xb[2 * NN + i];
    }
    __syncthreads();

    int lane = t & 31;
    int w = t >> 5;                 // partition id
    int q = blockIdx.x * 32 + lane;
    float qx = sx[q], qy = sy[q], qz = sz[q];
    float dl[KNN]; int il[KNN];
#pragma unroll
    for (int j = 0; j < KNN; j++) { dl[j] = CUDART_INF_F; il[j] = 0; }

    int cnt = 0;
    int mbeg = w << 10;
    int mend = mbeg + 1024;
    for (int m0 = mbeg; m0 < mend; m0 += 8) {
        float d[8];
#pragma unroll
        for (int u = 0; u < 8; u++) {
            int m = m0 + u;
            float dx = qx - sx[m], dy = qy - sy[m], dz = qz - sz[m];
            d[u] = fmaf(dx, dx, fmaf(dy, dy, dz * dz));
        }
        float thr = dl[KNN - 1];
#pragma unroll
        for (int u = 0; u < 8; u++) {
            if (d[u] < thr) { sbuf[cnt][t] = (unsigned short)(m0 + u); cnt++; }
        }
        if (__any_sync(0xffffffffu, cnt > 20)) {
            for (int i = 0; i < cnt; i++) {
                int m = sbuf[i][t];
                float dx = qx - sx[m], dy = qy - sy[m], dz = qz - sz[m];
                float dd = fmaf(dx, dx, fmaf(dy, dy, dz * dz));
                if (dd < dl[KNN - 1]) insert20(dl, il, dd, m);
            }
            cnt = 0;
        }
    }
    for (int i = 0; i < cnt; i++) {
        int m = sbuf[i][t];
        float dx = qx - sx[m], dy = qy - sy[m], dz = qz - sz[m];
        float dd = fmaf(dx, dx, fmaf(dy, dy, dz * dz));
        if (dd < dl[KNN - 1]) insert20(dl, il, dd, m);
    }

    __syncthreads();
    if (w != 0) {
        int col = lane + ((w - 1) << 5);
#pragma unroll
        for (int j = 0; j < KNN; j++) {
            mdist[j][col] = dl[j];
            midx[j][col] = (unsigned short)il[j];
        }
    }
    __syncthreads();

    if (w == 0) {
        for (int p = 0; p < 3; p++) {
            int col = lane + (p << 5);
#pragma unroll 4
            for (int j = 0; j < KNN; j++) {
                float dd = mdist[j][col];
                int m = midx[j][col];
                if (dd < dl[KNN - 1]) insert20(dl, il, dd, m);
            }
        }

        int base = (b * NN + q) * KNN;
#pragma unroll
        for (int j = 0; j < KNN; j++) g_idx[base + j] = il[j];

        // Edge moments: first moment (6) + upper-tri second moment (21).
        float acc[27];
#pragma unroll
        for (int i = 0; i < 27; i++) acc[i] = 0.f;
#pragma unroll
        for (int j = 0; j < KNN; j++) {
            int m = il[j];
            float e[6];
            e[0] = sx[m] - qx; e[1] = sy[m] - qy; e[2] = sz[m] - qz;
            e[3] = qx; e[4] = qy; e[5] = qz;
            int tt = 6;
#pragma unroll
            for (int a = 0; a < 6; a++) {
                acc[a] += e[a];
#pragma unroll
                for (int bb = a; bb < 6; bb++) acc[tt++] += e[a] * e[bb];
            }
        }
#pragma unroll
        for (int i = 0; i < 27; i++) {
#pragma unroll
            for (int o = 16; o > 0; o >>= 1)
                acc[i] += __shfl_xor_sync(0xffffffffu, acc[i], o);
        }
        if (lane == 0) {
#pragma unroll
            for (int i = 0; i < 27; i++) atomicAdd(&g_mom[i], acc[i]);
        }
    }
}

__global__ void stats1_kernel(const float* __restrict__ W1,
                              const float* __restrict__ gamma1,
                              const float* __restrict__ beta1) {
    int c = threadIdx.x;
    if (c >= 64) return;
    float w[6];
#pragma unroll
    for (int j = 0; j < 6; j++) w[j] = W1[c * 6 + j];
    float m = 0.f;
#pragma unroll
    for (int j = 0; j < 6; j++) m += w[j] * g_mom[j];
    m /= NTOT;
    float qv = 0.f;
    int t = 6;
#pragma unroll
    for (int a = 0; a < 6; a++) {
#pragma unroll
        for (int bb = a; bb < 6; bb++) {
            float coef = (a == bb) ? 1.f : 2.f;
            qv += coef * w[a] * w[bb] * g_mom[t++];
        }
    }
    qv /= NTOT;
    float var = qv - m * m;
    float s = gamma1[c] * rsqrtf(var + EPSV);
    g_scale1[c] = s;
    g_shift1[c] = fmaf(-m, s, beta1[c]);
}

// Main fused kernel. GEMV j-split arranged so lane-pair (jh=0/1) reads
// ADJACENT 16B blocks of a plain contiguous 256B g-row: every LDS.128 is a
// single wavefront (the +144B layout cost 2 wf/LDS). Lane jh covers
// j in {8i+4jh+0..3}; w2pk packed to match. h1-phase writes are stride-1.
__global__ __launch_bounds__(256, 3) void main_kernel(const float* __restrict__ x,
                                                      const float* __restrict__ W1,
                                                      const float* __restrict__ W2) {
    __shared__ __align__(16) float sraw[2][2][KNN][8];
    __shared__ __align__(128) float sg[2][KNN][64];
    __shared__ float schanS[64], schanQ[64];

    int tid = threadIdx.x;
    int h = tid >> 7;          // point-half
    int t = tid & 127;
    int lane = t & 31;
    int jh = lane & 1;         // j-half
    int cg = ((t >> 5) << 4) + (lane >> 1);   // GEMV channel
    int ch = t & 63;           // h1-phase channel
    int kb = t >> 6;           // h1-phase k parity

    int pt0 = blockIdx.x * PTS;
    int b = pt0 >> 12;
    int n0 = pt0 & (NN - 1);

    ull w2pk[16];
#pragma unroll
    for (int i = 0; i < 8; i++) {
        int j0 = 8 * i + 4 * jh;
        w2pk[2 * i]     = pack2(W2[cg * 64 + j0],     W2[cg * 64 + j0 + 1]);
        w2pk[2 * i + 1] = pack2(W2[cg * 64 + j0 + 2], W2[cg * 64 + j0 + 3]);
    }
    float wt[6];
#pragma unroll
    for (int j = 0; j < 6; j++) wt[j] = W1[ch * 6 + j];
    wt[3] -= wt[0]; wt[4] -= wt[1]; wt[5] -= wt[2];
    float s1 = g_scale1[ch], sh1 = g_shift1[ch];
    float sum2 = 0.f, ssq2 = 0.f;
    const float* xb = x + b * 3 * NN;
    int gbase = b * NN;

    if (tid < 64) { schanS[tid] = 0.f; schanQ[tid] = 0.f; }

    bool gat = (t < KNN);
    int nbn = 0;
    if (gat) {
        int pt = n0 + h;
        int nb = g_idx[(gbase + pt) * KNN + t];
        unsigned sa = (unsigned)__cvta_generic_to_shared(&sraw[0][h][t][0]);
        cp4(sa + 0,  xb + nb);
        cp4(sa + 4,  xb + NN + nb);
        cp4(sa + 8,  xb + 2 * NN + nb);
        cp4(sa + 12, xb + pt);
        cp4(sa + 16, xb + NN + pt);
        cp4(sa + 20, xb + 2 * NN + pt);
        asm volatile("cp.async.commit_group;");
        int pt1 = n0 + 2 + h;
        nbn = g_idx[(gbase + pt1) * KNN + t];
    }

    for (int p = 0; p < PTS; p += 2) {
        int cur = (p >> 1) & 1;
        int pt = n0 + p + h;
        int gi = gbase + pt;
        if (gat) {
            if (p + 2 < PTS) {
                int ptn = n0 + p + 2 + h;
                unsigned sa = (unsigned)__cvta_generic_to_shared(&sraw[cur ^ 1][h][t][0]);
                cp4(sa + 0,  xb + nbn);
                cp4(sa + 4,  xb + NN + nbn);
                cp4(sa + 8,  xb + 2 * NN + nbn);
                cp4(sa + 12, xb + ptn);
                cp4(sa + 16, xb + NN + ptn);
                cp4(sa + 20, xb + 2 * NN + ptn);
            }
            asm volatile("cp.async.commit_group;");
            int pt2 = (p + 4 < PTS) ? (n0 + p + 4 + h) : n0;
            nbn = g_idx[(gbase + pt2) * KNN + t];
            asm volatile("cp.async.wait_group 1;");
        }
        __syncthreads();
#pragma unroll
        for (int i = 0; i < 10; i++) {
            int k = kb + 2 * i;
            const float* e = sraw[cur][h][k];
            float hv = e[0] * wt[0];
            hv = fmaf(e[1], wt[1], hv);
            hv = fmaf(e[2], wt[2], hv);
            hv = fmaf(e[3], wt[3], hv);
            hv = fmaf(e[4], wt[4], hv);
            hv = fmaf(e[5], wt[5], hv);
            float v = fmaf(s1, hv, sh1);
            sg[h][k][ch] = fmaxf(v, SLOPE * v);
        }
        __syncthreads();
        float mx = -CUDART_INF_F, mn = CUDART_INF_F;
#pragma unroll 2
        for (int k = 0; k < KNN; k++) {
            const ulonglong2* gp = reinterpret_cast<const ulonglong2*>(&sg[h][k][0]);
            ull a0 = 0ull, a1 = 0ull, a2 = 0ull, a3 = 0ull;
#pragma unroll
            for (int i = 0; i < 8; i += 2) {
                ulonglong2 gA = gp[2 * i + jh];
                ulonglong2 gB = gp[2 * (i + 1) + jh];
                fma2(a0, gA.x, w2pk[2 * i + 0]);
                fma2(a1, gA.y, w2pk[2 * i + 1]);
                fma2(a2, gB.x, w2pk[2 * i + 2]);
                fma2(a3, gB.y, w2pk[2 * i + 3]);
            }
            ull s = add2(add2(a0, a1), add2(a2, a3));
            float flo, fhi;
            unpack2(s, flo, fhi);
            float hsum = flo + fhi;
            float other = __shfl_xor_sync(0xffffffffu, hsum, 1);
            float hv = hsum + other;
            mx = fmaxf(mx, hv);
            mn = fminf(mn, hv);
            if (jh == 0) { sum2 += hv; ssq2 = fmaf(hv, hv, ssq2); }
        }
        if (jh == 0) {
            g_maxb[gi * 64 + cg] = mx;
            g_minb[gi * 64 + cg] = mn;
        }
    }

    __syncthreads();
    if (jh == 0) {
        atomicAdd(&schanS[cg], sum2);
        atomicAdd(&schanQ[cg], ssq2);
    }
    __syncthreads();
    if (tid < 64) {
        atomicAdd(&g_sum2[tid],   schanS[tid]);
        atomicAdd(&g_sumsq2[tid], schanQ[tid]);
    }
}

__global__ void stats2_kernel(const float* __restrict__ gamma2,
                              const float* __restrict__ beta2) {
    int c = threadIdx.x;
    if (c >= 64) return;
    float mean = g_sum2[c] / NTOT;
    float var = g_sumsq2[c] / NTOT - mean * mean;
    float s = gamma2[c] * rsqrtf(var + EPSV);
    g_scale2[c] = s;
    g_shift2[c] = fmaf(-mean, s, beta2[c]);
}

__global__ __launch_bounds__(256) void out_kernel(float* __restrict__ out) {
    __shared__ float tile[64][65];
    int b = blockIdx.y;
    int n0 = blockIdx.x * 64;
    int tid = threadIdx.x;
#pragma unroll
    for (int i = 0; i < 16; i++) {
        int flat = i * 256 + tid;
        int cc = flat & 63;
        int nl = flat >> 6;
        float s = g_scale2[cc];
        int gi = (b * NN + n0 + nl) * 64 + cc;
        float v;
        if (s >= 0.f) v = g_maxb[gi]; else v = g_minb[gi];
        float u = fmaf(s, v, g_shift2[cc]);
        tile[nl][cc] = fmaxf(u, SLOPE * u);
    }
    __syncthreads();
#pragma unroll
    for (int i = 0; i < 16; i++) {
        int flat = i * 256 + tid;
        int nl = flat & 63;
        int cc = flat >> 6;
        out[(b * 64 + cc) * NN + n0 + nl] = tile[nl][cc];
    }
}

extern "C" void kernel_launch(void* const* d_in, const int* in_sizes, int n_in,
                              void* d_out, int out_size) {
    const float* x      = (const float*)d_in[0];
    const float* W1     = (const float*)d_in[1];
    const float* gamma1 = (const float*)d_in[2];
    const float* beta1  = (const float*)d_in[3];
    const float* W2     = (const float*)d_in[4];
    const float* gamma2 = (const float*)d_in[5];
    const float* beta2  = (const float*)d_in[6];
    float* out = (float*)d_out;

    zero_kernel<<<1, 64>>>();
    knn_kernel<<<dim3(NN / 32, BB), 128>>>(x);
    stats1_kernel<<<1, 64>>>(W1, gamma1, beta1);
    main_kernel<<<BB * NN / PTS, 256>>>(x, W1, W2);
    stats2_kernel<<<1, 64>>>(gamma2, beta2);
    out_kernel<<<dim3(NN / 64, BB), 256>>>(out);
}

// round 8
// speedup vs baseline: 1.1068x; 1.1068x over previous
#include <cuda_runtime.h>
#include <math_constants.h>

#define BB 8
#define NN 4096
#define KNN 20
#define EPSV 1e-5f
#define SLOPE 0.2f
#define NTOT ((float)(BB*NN*KNN))
#define PTS 32

typedef unsigned long long ull;

__device__ __forceinline__ void fma2(ull& d, ull a, ull b) {
    asm("fma.rn.f32x2 %0, %1, %2, %0;" : "+l"(d) : "l"(a), "l"(b));
}
__device__ __forceinline__ ull add2(ull a, ull b) {
    ull r; asm("add.rn.f32x2 %0, %1, %2;" : "=l"(r) : "l"(a), "l"(b)); return r;
}
__device__ __forceinline__ ull pack2(float lo, float hi) {
    ull r; asm("mov.b64 %0, {%1, %2};" : "=l"(r) : "f"(lo), "f"(hi)); return r;
}
__device__ __forceinline__ void unpack2(ull v, float& lo, float& hi) {
    asm("mov.b64 {%0, %1}, %2;" : "=f"(lo), "=f"(hi) : "l"(v));
}
__device__ __forceinline__ void cp4(unsigned dst, const float* src) {
    asm volatile("cp.async.ca.shared.global [%0], [%1], 4;" :: "r"(dst), "l"(src));
}

__device__ int   g_idx[BB*NN*KNN];
__device__ float g_mom[27];
__device__ float g_scale1[64], g_shift1[64];
__device__ float g_sum2[64], g_sumsq2[64];
__device__ float g_scale2[64], g_shift2[64];
__device__ float g_maxb[BB*NN*64];
__device__ float g_minb[BB*NN*64];

__global__ void zero_kernel() {
    int t = threadIdx.x;
    if (t < 27) g_mom[t] = 0.f;
    if (t < 64) { g_sum2[t] = 0.f; g_sumsq2[t] = 0.f; }
}

// Branchless PARALLEL insertion (depth ~2).
__device__ __forceinline__ void insert20(float (&dl)[KNN], int (&il)[KNN],
                                         float dd, int m) {
#pragma unroll
    for (int j = KNN - 1; j >= 1; j--) {
        bool b1 = dd < dl[j - 1];
        bool b2 = dd < dl[j];
        dl[j] = b1 ? dl[j - 1] : (b2 ? dd : dl[j]);
        il[j] = b1 ? il[j - 1] : (b2 ? m  : il[j]);
    }
    bool b0 = dd < dl[0];
    dl[0] = b0 ? dd : dl[0];
    il[0] = b0 ? m  : il[0];
}

// KNN (R3 best-measured version): thread-per-query single scan, smem
// candidate buffer, warp-vote batched drains, parallel insertion.
__global__ __launch_bounds__(128) void knn_kernel(const float* __restrict__ x) {
    __shared__ float sx[NN], sy[NN], sz[NN];
    __shared__ unsigned short sbuf[32][128];
    int b = blockIdx.y;
    int tid = threadIdx.x;
    const float* xb = x + b * 3 * NN;
    for (int i = tid; i < NN; i += 128) {
        sx[i] = xb[i];
        sy[i] = xb[NN + i];
        sz[i] = xb[2 * NN + i];
    }
    __syncthreads();

    int q = blockIdx.x * 128 + tid;
    float qx = sx[q], qy = sy[q], qz = sz[q];
    float dl[KNN]; int il[KNN];
#pragma unroll
    for (int j = 0; j < KNN; j++) { dl[j] = CUDART_INF_F; il[j] = 0; }

    int cnt = 0;
    for (int m0 = 0; m0 < NN; m0 += 8) {
        float d[8];
#pragma unroll
        for (int u = 0; u < 8; u++) {
            int m = m0 + u;
            float dx = qx - sx[m], dy = qy - sy[m], dz = qz - sz[m];
            d[u] = fmaf(dx, dx, fmaf(dy, dy, dz * dz));
        }
        float thr = dl[KNN - 1];
#pragma unroll
        for (int u = 0; u < 8; u++) {
            if (d[u] < thr) { sbuf[cnt][tid] = (unsigned short)(m0 + u); cnt++; }
        }
        if (__any_sync(0xffffffffu, cnt > 20)) {
            for (int i = 0; i < cnt; i++) {
                int m = sbuf[i][tid];
                float dx = qx - sx[m], dy = qy - sy[m], dz = qz - sz[m];
                float dd = fmaf(dx, dx, fmaf(dy, dy, dz * dz));
                if (dd < dl[KNN - 1]) insert20(dl, il, dd, m);
            }
            cnt = 0;
        }
    }
    for (int i = 0; i < cnt; i++) {
        int m = sbuf[i][tid];
        float dx = qx - sx[m], dy = qy - sy[m], dz = qz - sz[m];
        float dd = fmaf(dx, dx, fmaf(dy, dy, dz * dz));
        if (dd < dl[KNN - 1]) insert20(dl, il, dd, m);
    }

    int base = (b * NN + q) * KNN;
#pragma unroll
    for (int j = 0; j < KNN; j++) g_idx[base + j] = il[j];

    float acc[27];
#pragma unroll
    for (int i = 0; i < 27; i++) acc[i] = 0.f;
#pragma unroll
    for (int j = 0; j < KNN; j++) {
        int m = il[j];
        float e[6];
        e[0] = sx[m] - qx; e[1] = sy[m] - qy; e[2] = sz[m] - qz;
        e[3] = qx; e[4] = qy; e[5] = qz;
        int t = 6;
#pragma unroll
        for (int a = 0; a < 6; a++) {
            acc[a] += e[a];
#pragma unroll
            for (int bb = a; bb < 6; bb++) acc[t++] += e[a] * e[bb];
        }
    }
#pragma unroll
    for (int i = 0; i < 27; i++) {
#pragma unroll
        for (int o = 16; o > 0; o >>= 1)
            acc[i] += __shfl_xor_sync(0xffffffffu, acc[i], o);
    }
    if ((tid & 31) == 0) {
#pragma unroll
        for (int i = 0; i < 27; i++) atomicAdd(&g_mom[i], acc[i]);
    }
}

__global__ void stats1_kernel(const float* __restrict__ W1,
                              const float* __restrict__ gamma1,
                              const float* __restrict__ beta1) {
    int c = threadIdx.x;
    if (c >= 64) return;
    float w[6];
#pragma unroll
    for (int j = 0; j < 6; j++) w[j] = W1[c * 6 + j];
    float m = 0.f;
#pragma unroll
    for (int j = 0; j < 6; j++) m += w[j] * g_mom[j];
    m /= NTOT;
    float qv = 0.f;
    int t = 6;
#pragma unroll
    for (int a = 0; a < 6; a++) {
#pragma unroll
        for (int bb = a; bb < 6; bb++) {
            float coef = (a == bb) ? 1.f : 2.f;
            qv += coef * w[a] * w[bb] * g_mom[t++];
        }
    }
    qv /= NTOT;
    float var = qv - m * m;
    float s = gamma1[c] * rsqrtf(var + EPSV);
    g_scale1[c] = s;
    g_shift1[c] = fmaf(-m, s, beta1[c]);
}

// Main fused kernel. GEMV: 4-way j-split across quad lanes, 2 channels per
// lane (loaded g reused for both) -> 16 LDS wavefronts per point per k
// (half of R7) with only 32 weight registers. Quad lane jq reads 16B blocks
// {16*ii + 4*jq} so each LDS.128 instruction covers 64B in one line = 1 wf.
// Partial sums combined by shfl_xor 1 then 2; lane jq=0 keeps channel c0,
// jq=1 keeps c1.
__global__ __launch_bounds__(256, 3) void main_kernel(const float* __restrict__ x,
                                                      const float* __restrict__ W1,
                                                      const float* __restrict__ W2) {
    __shared__ __align__(16) float sraw[2][2][KNN][8];
    __shared__ __align__(128) float sg[2][KNN][64];
    __shared__ float schanS[64], schanQ[64];

    int tid = threadIdx.x;
    int h = tid >> 7;            // point-half
    int t = tid & 127;
    int lane = t & 31;
    int wg = t >> 5;             // warp within point (0..3)
    int jq = lane & 3;           // j-quarter
    int pg = lane >> 2;          // channel pair group (0..7)
    int c0 = wg * 16 + pg * 2;   // this lane's channel pair: c0, c0+1
    int ch = t & 63;             // h1-phase channel
    int kb = t >> 6;             // h1-phase k parity

    int pt0 = blockIdx.x * PTS;
    int b = pt0 >> 12;
    int n0 = pt0 & (NN - 1);

    // weights: channel c0 and c0+1, j in {16*ii + 4*jq + 0..3}
    ull wA[8], wB[8];
#pragma unroll
    for (int ii = 0; ii < 4; ii++) {
        int j0 = 16 * ii + 4 * jq;
        wA[2 * ii]     = pack2(W2[c0 * 64 + j0],     W2[c0 * 64 + j0 + 1]);
        wA[2 * ii + 1] = pack2(W2[c0 * 64 + j0 + 2], W2[c0 * 64 + j0 + 3]);
        wB[2 * ii]     = pack2(W2[(c0 + 1) * 64 + j0],     W2[(c0 + 1) * 64 + j0 + 1]);
        wB[2 * ii + 1] = pack2(W2[(c0 + 1) * 64 + j0 + 2], W2[(c0 + 1) * 64 + j0 + 3]);
    }
    float wt[6];
#pragma unroll
    for (int j = 0; j < 6; j++) wt[j] = W1[ch * 6 + j];
    wt[3] -= wt[0]; wt[4] -= wt[1]; wt[5] -= wt[2];
    float s1 = g_scale1[ch], sh1 = g_shift1[ch];
    float sum2 = 0.f, ssq2 = 0.f;
    const float* xb = x + b * 3 * NN;
    int gbase = b * NN;
    int cmine = c0 + (jq & 1);   // channel this lane tracks (jq 0 -> c0, jq 1 -> c1)

    if (tid < 64) { schanS[tid] = 0.f; schanQ[tid] = 0.f; }

    bool gat = (t < KNN);
    int nbn = 0;
    if (gat) {
        int pt = n0 + h;
        int nb = g_idx[(gbase + pt) * KNN + t];
        unsigned sa = (unsigned)__cvta_generic_to_shared(&sraw[0][h][t][0]);
        cp4(sa + 0,  xb + nb);
        cp4(sa + 4,  xb + NN + nb);
        cp4(sa + 8,  xb + 2 * NN + nb);
        cp4(sa + 12, xb + pt);
        cp4(sa + 16, xb + NN + pt);
        cp4(sa + 20, xb + 2 * NN + pt);
        asm volatile("cp.async.commit_group;");
        int pt1 = n0 + 2 + h;
        nbn = g_idx[(gbase + pt1) * KNN + t];
    }

    for (int p = 0; p < PTS; p += 2) {
        int cur = (p >> 1) & 1;
        int pt = n0 + p + h;
        int gi = gbase + pt;
        if (gat) {
            if (p + 2 < PTS) {
                int ptn = n0 + p + 2 + h;
                unsigned sa = (unsigned)__cvta_generic_to_shared(&sraw[cur ^ 1][h][t][0]);
                cp4(sa + 0,  xb + nbn);
                cp4(sa + 4,  xb + NN + nbn);
                cp4(sa + 8,  xb + 2 * NN + nbn);
                cp4(sa + 12, xb + ptn);
                cp4(sa + 16, xb + NN + ptn);
                cp4(sa + 20, xb + 2 * NN + ptn);
            }
            asm volatile("cp.async.commit_group;");
            int pt2 = (p + 4 < PTS) ? (n0 + p + 4 + h) : n0;
            nbn = g_idx[(gbase + pt2) * KNN + t];
            asm volatile("cp.async.wait_group 1;");
        }
        __syncthreads();
#pragma unroll
        for (int i = 0; i < 10; i++) {
            int k = kb + 2 * i;
            const float* e = sraw[cur][h][k];
            float hv = e[0] * wt[0];
            hv = fmaf(e[1], wt[1], hv);
            hv = fmaf(e[2], wt[2], hv);
            hv = fmaf(e[3], wt[3], hv);
            hv = fmaf(e[4], wt[4], hv);
            hv = fmaf(e[5], wt[5], hv);
            float v = fmaf(s1, hv, sh1);
            sg[h][k][ch] = fmaxf(v, SLOPE * v);
        }
        __syncthreads();
        float mx = -CUDART_INF_F, mn = CUDART_INF_F;
#pragma unroll 2
        for (int k = 0; k < KNN; k++) {
            const float* row = &sg[h][k][0];
            ull a0 = 0ull, a1 = 0ull, b0 = 0ull, b1 = 0ull;
#pragma unroll
            for (int ii = 0; ii < 4; ii++) {
                ulonglong2 gv = *reinterpret_cast<const ulonglong2*>(row + 16 * ii + 4 * jq);
                fma2(a0, gv.x, wA[2 * ii]);
                fma2(a1, gv.y, wA[2 * ii + 1]);
                fma2(b0, gv.x, wB[2 * ii]);
                fma2(b1, gv.y, wB[2 * ii + 1]);
            }
            float alo, ahi, blo, bhi;
            unpack2(add2(a0, a1), alo, ahi);
            unpack2(add2(b0, b1), blo, bhi);
            float hA = alo + ahi;
            float hB = blo + bhi;
            hA += __shfl_xor_sync(0xffffffffu, hA, 1);
            hA += __shfl_xor_sync(0xffffffffu, hA, 2);
            hB += __shfl_xor_sync(0xffffffffu, hB, 1);
            hB += __shfl_xor_sync(0xffffffffu, hB, 2);
            float hv = (jq & 1) ? hB : hA;
            mx = fmaxf(mx, hv);
            mn = fminf(mn, hv);
            if (jq < 2) { sum2 += hv; ssq2 = fmaf(hv, hv, ssq2); }
        }
        if (jq < 2) {
            g_maxb[gi * 64 + cmine] = mx;
            g_minb[gi * 64 + cmine] = mn;
        }
    }

    __syncthreads();
    if (jq < 2) {
        atomicAdd(&schanS[cmine], sum2);
        atomicAdd(&schanQ[cmine], ssq2);
    }
    __syncthreads();
    if (tid < 64) {
        atomicAdd(&g_sum2[tid],   schanS[tid]);
        atomicAdd(&g_sumsq2[tid], schanQ[tid]);
    }
}

__global__ void stats2_kernel(const float* __restrict__ gamma2,
                              const float* __restrict__ beta2) {
    int c = threadIdx.x;
    if (c >= 64) return;
    float mean = g_sum2[c] / NTOT;
    float var = g_sumsq2[c] / NTOT - mean * mean;
    float s = gamma2[c] * rsqrtf(var + EPSV);
    g_scale2[c] = s;
    g_shift2[c] = fmaf(-mean, s, beta2[c]);
}

__global__ __launch_bounds__(256) void out_kernel(float* __restrict__ out) {
    __shared__ float tile[64][65];
    int b = blockIdx.y;
    int n0 = blockIdx.x * 64;
    int tid = threadIdx.x;
#pragma unroll
    for (int i = 0; i < 16; i++) {
        int flat = i * 256 + tid;
        int cc = flat & 63;
        int nl = flat >> 6;
        float s = g_scale2[cc];
        int gi = (b * NN + n0 + nl) * 64 + cc;
        float v;
        if (s >= 0.f) v = g_maxb[gi]; else v = g_minb[gi];
        float u = fmaf(s, v, g_shift2[cc]);
        tile[nl][cc] = fmaxf(u, SLOPE * u);
    }
    __syncthreads();
#pragma unroll
    for (int i = 0; i < 16; i++) {
        int flat = i * 256 + tid;
        int nl = flat & 63;
        int cc = flat >> 6;
        out[(b * 64 + cc) * NN + n0 + nl] = tile[nl][cc];
    }
}

extern "C" void kernel_launch(void* const* d_in, const int* in_sizes, int n_in,
                              void* d_out, int out_size) {
    const float* x      = (const float*)d_in[0];
    const float* W1     = (const float*)d_in[1];
    const float* gamma1 = (const float*)d_in[2];
    const float* beta1  = (const float*)d_in[3];
    const float* W2     = (const float*)d_in[4];
    const float* gamma2 = (const float*)d_in[5];
    const float* beta2  = (const float*)d_in[6];
    float* out = (float*)d_out;

    zero_kernel<<<1, 64>>>();
    knn_kernel<<<dim3(NN / 128, BB), 128>>>(x);
    stats1_kernel<<<1, 64>>>(W1, gamma1, beta1);
    main_kernel<<<BB * NN / PTS, 256>>>(x, W1, W2);
    stats2_kernel<<<1, 64>>>(gamma2, beta2);
    out_kernel<<<dim3(NN / 64, BB), 256>>>(out);
}

// round 9
// speedup vs baseline: 1.2444x; 1.1243x over previous
#include <cuda_runtime.h>
#include <math_constants.h>

#define BB 8
#define NN 4096
#define KNN 20
#define EPSV 1e-5f
#define SLOPE 0.2f
#define NTOT ((float)(BB*NN*KNN))
#define PTS 32

typedef unsigned long long ull;

__device__ __forceinline__ void fma2(ull& d, ull a, ull b) {
    asm("fma.rn.f32x2 %0, %1, %2, %0;" : "+l"(d) : "l"(a), "l"(b));
}
__device__ __forceinline__ ull add2(ull a, ull b) {
    ull r; asm("add.rn.f32x2 %0, %1, %2;" : "=l"(r) : "l"(a), "l"(b)); return r;
}
__device__ __forceinline__ ull pack2(float lo, float hi) {
    ull r; asm("mov.b64 %0, {%1, %2};" : "=l"(r) : "f"(lo), "f"(hi)); return r;
}
__device__ __forceinline__ void unpack2(ull v, float& lo, float& hi) {
    asm("mov.b64 {%0, %1}, %2;" : "=f"(lo), "=f"(hi) : "l"(v));
}
__device__ __forceinline__ void cp4(unsigned dst, const float* src) {
    asm volatile("cp.async.ca.shared.global [%0], [%1], 4;" :: "r"(dst), "l"(src));
}

__device__ int   g_idx[BB*NN*KNN];
__device__ float g_mom[27];
__device__ float g_scale1[64], g_shift1[64];
__device__ float g_sum2[64], g_sumsq2[64];
__device__ float g_scale2[64], g_shift2[64];
__device__ float g_maxb[BB*NN*64];
__device__ float g_minb[BB*NN*64];

__global__ void zero_kernel() {
    int t = threadIdx.x;
    if (t < 27) g_mom[t] = 0.f;
    if (t < 64) { g_sum2[t] = 0.f; g_sumsq2[t] = 0.f; }
}

// Branchless PARALLEL insertion (depth ~2).
__device__ __forceinline__ void insert20(float (&dl)[KNN], int (&il)[KNN],
                                         float dd, int m) {
#pragma unroll
    for (int j = KNN - 1; j >= 1; j--) {
        bool b1 = dd < dl[j - 1];
        bool b2 = dd < dl[j];
        dl[j] = b1 ? dl[j - 1] : (b2 ? dd : dl[j]);
        il[j] = b1 ? il[j - 1] : (b2 ? m  : il[j]);
    }
    bool b0 = dd < dl[0];
    dl[0] = b0 ? dd : dl[0];
    il[0] = b0 ? m  : il[0];
}

// KNN: thread-per-query single scan; distance in inner-product s-space
// s(m) = |m|^2 - 2 q.m  (monotone shift of d per query -> same selection,
// same ascending-m strict-'<' ties). 8 evals per iter via float4 broadcast
// loads (8 LDS.128) + 12 fma.f32x2. Warp-vote batched drains.
__global__ __launch_bounds__(128) void knn_kernel(const float* __restrict__ x) {
    __shared__ __align__(16) float sx[NN], sy[NN], sz[NN], sq[NN];
    __shared__ unsigned short sbuf[32][128];
    int b = blockIdx.y;
    int tid = threadIdx.x;
    const float* xb = x + b * 3 * NN;
    for (int i = tid; i < NN; i += 128) {
        float xv = xb[i], yv = xb[NN + i], zv = xb[2 * NN + i];
        sx[i] = xv; sy[i] = yv; sz[i] = zv;
        sq[i] = fmaf(xv, xv, fmaf(yv, yv, zv * zv));
    }
    __syncthreads();

    int q = blockIdx.x * 128 + tid;
    float qx = sx[q], qy = sy[q], qz = sz[q];
    float n2x = -2.f * qx, n2y = -2.f * qy, n2z = -2.f * qz;
    ull qx2 = pack2(n2x, n2x), qy2 = pack2(n2y, n2y), qz2 = pack2(n2z, n2z);
    float dl[KNN]; int il[KNN];
#pragma unroll
    for (int j = 0; j < KNN; j++) { dl[j] = CUDART_INF_F; il[j] = 0; }

    const ulonglong2* X4 = reinterpret_cast<const ulonglong2*>(sx);
    const ulonglong2* Y4 = reinterpret_cast<const ulonglong2*>(sy);
    const ulonglong2* Z4 = reinterpret_cast<const ulonglong2*>(sz);
    const ulonglong2* Q4 = reinterpret_cast<const ulonglong2*>(sq);

    int cnt = 0;
    for (int m0 = 0; m0 < NN; m0 += 8) {
        int g0 = m0 >> 2;
        ulonglong2 xA = X4[g0], xB = X4[g0 + 1];
        ulonglong2 yA = Y4[g0], yB = Y4[g0 + 1];
        ulonglong2 zA = Z4[g0], zB = Z4[g0 + 1];
        ulonglong2 qA = Q4[g0], qB = Q4[g0 + 1];
        ull s0 = qA.x, s1 = qA.y, s2 = qB.x, s3 = qB.y;
        fma2(s0, xA.x, qx2); fma2(s0, yA.x, qy2); fma2(s0, zA.x, qz2);
        fma2(s1, xA.y, qx2); fma2(s1, yA.y, qy2); fma2(s1, zA.y, qz2);
        fma2(s2, xB.x, qx2); fma2(s2, yB.x, qy2); fma2(s2, zB.x, qz2);
        fma2(s3, xB.y, qx2); fma2(s3, yB.y, qy2); fma2(s3, zB.y, qz2);
        float thr = dl[KNN - 1];
        float e0, e1, e2, e3, e4, e5, e6, e7;
        unpack2(s0, e0, e1); unpack2(s1, e2, e3);
        unpack2(s2, e4, e5); unpack2(s3, e6, e7);
        if (e0 < thr) { sbuf[cnt][tid] = (unsigned short)(m0 + 0); cnt++; }
        if (e1 < thr) { sbuf[cnt][tid] = (unsigned short)(m0 + 1); cnt++; }
        if (e2 < thr) { sbuf[cnt][tid] = (unsigned short)(m0 + 2); cnt++; }
        if (e3 < thr) { sbuf[cnt][tid] = (unsigned short)(m0 + 3); cnt++; }
        if (e4 < thr) { sbuf[cnt][tid] = (unsigned short)(m0 + 4); cnt++; }
        if (e5 < thr) { sbuf[cnt][tid] = (unsigned short)(m0 + 5); cnt++; }
        if (e6 < thr) { sbuf[cnt][tid] = (unsigned short)(m0 + 6); cnt++; }
        if (e7 < thr) { sbuf[cnt][tid] = (unsigned short)(m0 + 7); cnt++; }
        if (__any_sync(0xffffffffu, cnt > 20)) {
            for (int i = 0; i < cnt; i++) {
                int m = sbuf[i][tid];
                float ss = sq[m];
                ss = fmaf(sx[m], n2x, ss);
                ss = fmaf(sy[m], n2y, ss);
                ss = fmaf(sz[m], n2z, ss);
                if (ss < dl[KNN - 1]) insert20(dl, il, ss, m);
            }
            cnt = 0;
        }
    }
    for (int i = 0; i < cnt; i++) {
        int m = sbuf[i][tid];
        float ss = sq[m];
        ss = fmaf(sx[m], n2x, ss);
        ss = fmaf(sy[m], n2y, ss);
        ss = fmaf(sz[m], n2z, ss);
        if (ss < dl[KNN - 1]) insert20(dl, il, ss, m);
    }

    int base = (b * NN + q) * KNN;
#pragma unroll
    for (int j = 0; j < KNN; j++) g_idx[base + j] = il[j];

    // Edge moments: first moment (6) + upper-tri second moment (21).
    float acc[27];
#pragma unroll
    for (int i = 0; i < 27; i++) acc[i] = 0.f;
#pragma unroll
    for (int j = 0; j < KNN; j++) {
        int m = il[j];
        float e[6];
        e[0] = sx[m] - qx; e[1] = sy[m] - qy; e[2] = sz[m] - qz;
        e[3] = qx; e[4] = qy; e[5] = qz;
        int t = 6;
#pragma unroll
        for (int a = 0; a < 6; a++) {
            acc[a] += e[a];
#pragma unroll
            for (int bb = a; bb < 6; bb++) acc[t++] += e[a] * e[bb];
        }
    }
#pragma unroll
    for (int i = 0; i < 27; i++) {
#pragma unroll
        for (int o = 16; o > 0; o >>= 1)
            acc[i] += __shfl_xor_sync(0xffffffffu, acc[i], o);
    }
    if ((tid & 31) == 0) {
#pragma unroll
        for (int i = 0; i < 27; i++) atomicAdd(&g_mom[i], acc[i]);
    }
}

__global__ void stats1_kernel(const float* __restrict__ W1,
                              const float* __restrict__ gamma1,
                              const float* __restrict__ beta1) {
    int c = threadIdx.x;
    if (c >= 64) return;
    float w[6];
#pragma unroll
    for (int j = 0; j < 6; j++) w[j] = W1[c * 6 + j];
    float m = 0.f;
#pragma unroll
    for (int j = 0; j < 6; j++) m += w[j] * g_mom[j];
    m /= NTOT;
    float qv = 0.f;
    int t = 6;
#pragma unroll
    for (int a = 0; a < 6; a++) {
#pragma unroll
        for (int bb = a; bb < 6; bb++) {
            float coef = (a == bb) ? 1.f : 2.f;
            qv += coef * w[a] * w[bb] * g_mom[t++];
        }
    }
    qv /= NTOT;
    float var = qv - m * m;
    float s = gamma1[c] * rsqrtf(var + EPSV);
    g_scale1[c] = s;
    g_shift1[c] = fmaf(-m, s, beta1[c]);
}

// Main fused kernel (R7 best-measured version): jh 2-way split, contiguous
// sg rows so lane-pair reads adjacent 16B blocks (1 wavefront per LDS.128).
__global__ __launch_bounds__(256, 3) void main_kernel(const float* __restrict__ x,
                                                      const float* __restrict__ W1,
                                                      const float* __restrict__ W2) {
    __shared__ __align__(16) float sraw[2][2][KNN][8];
    __shared__ __align__(128) float sg[2][KNN][64];
    __shared__ float schanS[64], schanQ[64];

    int tid = threadIdx.x;
    int h = tid >> 7;          // point-half
    int t = tid & 127;
    int lane = t & 31;
    int jh = lane & 1;         // j-half
    int cg = ((t >> 5) << 4) + (lane >> 1);   // GEMV channel
    int ch = t & 63;           // h1-phase channel
    int kb = t >> 6;           // h1-phase k parity

    int pt0 = blockIdx.x * PTS;
    int b = pt0 >> 12;
    int n0 = pt0 & (NN - 1);

    ull w2pk[16];
#pragma unroll
    for (int i = 0; i < 8; i++) {
        int j0 = 8 * i + 4 * jh;
        w2pk[2 * i]     = pack2(W2[cg * 64 + j0],     W2[cg * 64 + j0 + 1]);
        w2pk[2 * i + 1] = pack2(W2[cg * 64 + j0 + 2], W2[cg * 64 + j0 + 3]);
    }
    float wt[6];
#pragma unroll
    for (int j = 0; j < 6; j++) wt[j] = W1[ch * 6 + j];
    wt[3] -= wt[0]; wt[4] -= wt[1]; wt[5] -= wt[2];
    float s1 = g_scale1[ch], sh1 = g_shift1[ch];
    float sum2 = 0.f, ssq2 = 0.f;
    const float* xb = x + b * 3 * NN;
    int gbase = b * NN;

    if (tid < 64) { schanS[tid] = 0.f; schanQ[tid] = 0.f; }

    bool gat = (t < KNN);
    int nbn = 0;
    if (gat) {
        int pt = n0 + h;
        int nb = g_idx[(gbase + pt) * KNN + t];
        unsigned sa = (unsigned)__cvta_generic_to_shared(&sraw[0][h][t][0]);
        cp4(sa + 0,  xb + nb);
        cp4(sa + 4,  xb + NN + nb);
        cp4(sa + 8,  xb + 2 * NN + nb);
        cp4(sa + 12, xb + pt);
        cp4(sa + 16, xb + NN + pt);
        cp4(sa + 20, xb + 2 * NN + pt);
        asm volatile("cp.async.commit_group;");
        int pt1 = n0 + 2 + h;
        nbn = g_idx[(gbase + pt1) * KNN + t];
    }

    for (int p = 0; p < PTS; p += 2) {
        int cur = (p >> 1) & 1;
        int pt = n0 + p + h;
        int gi = gbase + pt;
        if (gat) {
            if (p + 2 < PTS) {
                int ptn = n0 + p + 2 + h;
                unsigned sa = (unsigned)__cvta_generic_to_shared(&sraw[cur ^ 1][h][t][0]);
                cp4(sa + 0,  xb + nbn);
                cp4(sa + 4,  xb + NN + nbn);
                cp4(sa + 8,  xb + 2 * NN + nbn);
                cp4(sa + 12, xb + ptn);
                cp4(sa + 16, xb + NN + ptn);
                cp4(sa + 20, xb + 2 * NN + ptn);
            }
            asm volatile("cp.async.commit_group;");
            int pt2 = (p + 4 < PTS) ? (n0 + p + 4 + h) : n0;
            nbn = g_idx[(gbase + pt2) * KNN + t];
            asm volatile("cp.async.wait_group 1;");
        }
        __syncthreads();
#pragma unroll
        for (int i = 0; i < 10; i++) {
            int k = kb + 2 * i;
            const float* e = sraw[cur][h][k];
            float hv = e[0] * wt[0];
            hv = fmaf(e[1], wt[1], hv);
            hv = fmaf(e[2], wt[2], hv);
            hv = fmaf(e[3], wt[3], hv);
            hv = fmaf(e[4], wt[4], hv);
            hv = fmaf(e[5], wt[5], hv);
            float v = fmaf(s1, hv, sh1);
            sg[h][k][ch] = fmaxf(v, SLOPE * v);
        }
        __syncthreads();
        float mx = -CUDART_INF_F, mn = CUDART_INF_F;
#pragma unroll 2
        for (int k = 0; k < KNN; k++) {
            const ulonglong2* gp = reinterpret_cast<const ulonglong2*>(&sg[h][k][0]);
            ull a0 = 0ull, a1 = 0ull, a2 = 0ull, a3 = 0ull;
#pragma unroll
            for (int i = 0; i < 8; i += 2) {
                ulonglong2 gA = gp[2 * i + jh];
                ulonglong2 gB = gp[2 * (i + 1) + jh];
                fma2(a0, gA.x, w2pk[2 * i + 0]);
                fma2(a1, gA.y, w2pk[2 * i + 1]);
                fma2(a2, gB.x, w2pk[2 * i + 2]);
                fma2(a3, gB.y, w2pk[2 * i + 3]);
            }
            ull s = add2(add2(a0, a1), add2(a2, a3));
            float flo, fhi;
            unpack2(s, flo, fhi);
            float hsum = flo + fhi;
            float other = __shfl_xor_sync(0xffffffffu, hsum, 1);
            float hv = hsum + other;
            mx = fmaxf(mx, hv);
            mn = fminf(mn, hv);
            if (jh == 0) { sum2 += hv; ssq2 = fmaf(hv, hv, ssq2); }
        }
        if (jh == 0) {
            g_maxb[gi * 64 + cg] = mx;
            g_minb[gi * 64 + cg] = mn;
        }
    }

    __syncthreads();
    if (jh == 0) {
        atomicAdd(&schanS[cg], sum2);
        atomicAdd(&schanQ[cg], ssq2);
    }
    __syncthreads();
    if (tid < 64) {
        atomicAdd(&g_sum2[tid],   schanS[tid]);
        atomicAdd(&g_sumsq2[tid], schanQ[tid]);
    }
}

__global__ void stats2_kernel(const float* __restrict__ gamma2,
                              const float* __restrict__ beta2) {
    int c = threadIdx.x;
    if (c >= 64) return;
    float mean = g_sum2[c] / NTOT;
    float var = g_sumsq2[c] / NTOT - mean * mean;
    float s = gamma2[c] * rsqrtf(var + EPSV);
    g_scale2[c] = s;
    g_shift2[c] = fmaf(-mean, s, beta2[c]);
}

__global__ __launch_bounds__(256) void out_kernel(float* __restrict__ out) {
    __shared__ float tile[64][65];
    int b = blockIdx.y;
    int n0 = blockIdx.x * 64;
    int tid = threadIdx.x;
#pragma unroll
    for (int i = 0; i < 16; i++) {
        int flat = i * 256 + tid;
        int cc = flat & 63;
        int nl = flat >> 6;
        float s = g_scale2[cc];
        int gi = (b * NN + n0 + nl) * 64 + cc;
        float v;
        if (s >= 0.f) v = g_maxb[gi]; else v = g_minb[gi];
        float u = fmaf(s, v, g_shift2[cc]);
        tile[nl][cc] = fmaxf(u, SLOPE * u);
    }
    __syncthreads();
#pragma unroll
    for (int i = 0; i < 16; i++) {
        int flat = i * 256 + tid;
        int nl = flat & 63;
        int cc = flat >> 6;
        out[(b * 64 + cc) * NN + n0 + nl] = tile[nl][cc];
    }
}

extern "C" void kernel_launch(void* const* d_in, const int* in_sizes, int n_in,
                              void* d_out, int out_size) {
    const float* x      = (const float*)d_in[0];
    const float* W1     = (const float*)d_in[1];
    const float* gamma1 = (const float*)d_in[2];
    const float* beta1  = (const float*)d_in[3];
    const float* W2     = (const float*)d_in[4];
    const float* gamma2 = (const float*)d_in[5];
    const float* beta2  = (const float*)d_in[6];
    float* out = (float*)d_out;

    zero_kernel<<<1, 64>>>();
    knn_kernel<<<dim3(NN / 128, BB), 128>>>(x);
    stats1_kernel<<<1, 64>>>(W1, gamma1, beta1);
    main_kernel<<<BB * NN / PTS, 256>>>(x, W1, W2);
    stats2_kernel<<<1, 64>>>(gamma2, beta2);
    out_kernel<<<dim3(NN / 64, BB), 256>>>(out);
}

// round 11
// speedup vs baseline: 1.8206x; 1.4631x over previous
#include <cuda_runtime.h>
#include <math_constants.h>
#include <cstdint>

#define BB 8
#define NN 4096
#define KNN 20
#define EPSV 1e-5f
#define SLOPE 0.2f
#define NTOT ((float)(BB*NN*KNN))
#define PTS 32

typedef unsigned long long ull;

__device__ __forceinline__ void fma2(ull& d, ull a, ull b) {
    asm("fma.rn.f32x2 %0, %1, %2, %0;" : "+l"(d) : "l"(a), "l"(b));
}
__device__ __forceinline__ ull pack2(float lo, float hi) {
    ull r; asm("mov.b64 %0, {%1, %2};" : "=l"(r) : "f"(lo), "f"(hi)); return r;
}
__device__ __forceinline__ void unpack2(ull v, float& lo, float& hi) {
    asm("mov.b64 {%0, %1}, %2;" : "=f"(lo), "=f"(hi) : "l"(v));
}
__device__ __forceinline__ uint32_t smem_u32(const void* p) {
    uint32_t a;
    asm("{ .reg .u64 t; cvta.to.shared.u64 t, %1; cvt.u32.u64 %0, t; }"
        : "=r"(a) : "l"(p));
    return a;
}
// bf16x2 pack: lo half = a, hi half = b
__device__ __forceinline__ uint32_t bf2(float a, float b) {
    uint32_t r;
    asm("cvt.rn.bf16x2.f32 %0, %1, %2;" : "=r"(r) : "f"(b), "f"(a));
    return r;
}

__device__ int   g_idx[BB*NN*KNN];
__device__ float g_mom[27];
__device__ float g_scale1[64], g_shift1[64];
__device__ float g_sum2[64], g_sumsq2[64];
__device__ float g_scale2[64], g_shift2[64];
__device__ float g_maxb[BB*NN*64];
__device__ float g_minb[BB*NN*64];

__global__ void zero_kernel() {
    int t = threadIdx.x;
    if (t < 27) g_mom[t] = 0.f;
    if (t < 64) { g_sum2[t] = 0.f; g_sumsq2[t] = 0.f; }
}

__device__ __forceinline__ void insert20(float (&dl)[KNN], int (&il)[KNN],
                                         float dd, int m) {
#pragma unroll
    for (int j = KNN - 1; j >= 1; j--) {
        bool b1 = dd < dl[j - 1];
        bool b2 = dd < dl[j];
        dl[j] = b1 ? dl[j - 1] : (b2 ? dd : dl[j]);
        il[j] = b1 ? il[j - 1] : (b2 ? m  : il[j]);
    }
    bool b0 = dd < dl[0];
    dl[0] = b0 ? dd : dl[0];
    il[0] = b0 ? m  : il[0];
}

// KNN (R9 version, measured best): s-space distances, float4 broadcast loads,
// f32x2 math, warp-vote batched drains.
__global__ __launch_bounds__(128) void knn_kernel(const float* __restrict__ x) {
    __shared__ __align__(16) float sx[NN], sy[NN], sz[NN], sq[NN];
    __shared__ unsigned short sbuf[32][128];
    int b = blockIdx.y;
    int tid = threadIdx.x;
    const float* xb = x + b * 3 * NN;
    for (int i = tid; i < NN; i += 128) {
        float xv = xb[i], yv = xb[NN + i], zv = xb[2 * NN + i];
        sx[i] = xv; sy[i] = yv; sz[i] = zv;
        sq[i] = fmaf(xv, xv, fmaf(yv, yv, zv * zv));
    }
    __syncthreads();

    int q = blockIdx.x * 128 + tid;
    float qx = sx[q], qy = sy[q], qz = sz[q];
    float n2x = -2.f * qx, n2y = -2.f * qy, n2z = -2.f * qz;
    ull qx2 = pack2(n2x, n2x), qy2 = pack2(n2y, n2y), qz2 = pack2(n2z, n2z);
    float dl[KNN]; int il[KNN];
#pragma unroll
    for (int j = 0; j < KNN; j++) { dl[j] = CUDART_INF_F; il[j] = 0; }

    const ulonglong2* X4 = reinterpret_cast<const ulonglong2*>(sx);
    const ulonglong2* Y4 = reinterpret_cast<const ulonglong2*>(sy);
    const ulonglong2* Z4 = reinterpret_cast<const ulonglong2*>(sz);
    const ulonglong2* Q4 = reinterpret_cast<const ulonglong2*>(sq);

    int cnt = 0;
    for (int m0 = 0; m0 < NN; m0 += 8) {
        int g0 = m0 >> 2;
        ulonglong2 xA = X4[g0], xB = X4[g0 + 1];
        ulonglong2 yA = Y4[g0], yB = Y4[g0 + 1];
        ulonglong2 zA = Z4[g0], zB = Z4[g0 + 1];
        ulonglong2 qA = Q4[g0], qB = Q4[g0 + 1];
        ull s0 = qA.x, s1 = qA.y, s2 = qB.x, s3 = qB.y;
        fma2(s0, xA.x, qx2); fma2(s0, yA.x, qy2); fma2(s0, zA.x, qz2);
        fma2(s1, xA.y, qx2); fma2(s1, yA.y, qy2); fma2(s1, zA.y, qz2);
        fma2(s2, xB.x, qx2); fma2(s2, yB.x, qy2); fma2(s2, zB.x, qz2);
        fma2(s3, xB.y, qx2); fma2(s3, yB.y, qy2); fma2(s3, zB.y, qz2);
        float thr = dl[KNN - 1];
        float e0, e1, e2, e3, e4, e5, e6, e7;
        unpack2(s0, e0, e1); unpack2(s1, e2, e3);
        unpack2(s2, e4, e5); unpack2(s3, e6, e7);
        if (e0 < thr) { sbuf[cnt][tid] = (unsigned short)(m0 + 0); cnt++; }
        if (e1 < thr) { sbuf[cnt][tid] = (unsigned short)(m0 + 1); cnt++; }
        if (e2 < thr) { sbuf[cnt][tid] = (unsigned short)(m0 + 2); cnt++; }
        if (e3 < thr) { sbuf[cnt][tid] = (unsigned short)(m0 + 3); cnt++; }
        if (e4 < thr) { sbuf[cnt][tid] = (unsigned short)(m0 + 4); cnt++; }
        if (e5 < thr) { sbuf[cnt][tid] = (unsigned short)(m0 + 5); cnt++; }
        if (e6 < thr) { sbuf[cnt][tid] = (unsigned short)(m0 + 6); cnt++; }
        if (e7 < thr) { sbuf[cnt][tid] = (unsigned short)(m0 + 7); cnt++; }
        if (__any_sync(0xffffffffu, cnt > 20)) {
            for (int i = 0; i < cnt; i++) {
                int m = sbuf[i][tid];
                float ss = sq[m];
                ss = fmaf(sx[m], n2x, ss);
                ss = fmaf(sy[m], n2y, ss);
                ss = fmaf(sz[m], n2z, ss);
                if (ss < dl[KNN - 1]) insert20(dl, il, ss, m);
            }
            cnt = 0;
        }
    }
    for (int i = 0; i < cnt; i++) {
        int m = sbuf[i][tid];
        float ss = sq[m];
        ss = fmaf(sx[m], n2x, ss);
        ss = fmaf(sy[m], n2y, ss);
        ss = fmaf(sz[m], n2z, ss);
        if (ss < dl[KNN - 1]) insert20(dl, il, ss, m);
    }

    int base = (b * NN + q) * KNN;
#pragma unroll
    for (int j = 0; j < KNN; j++) g_idx[base + j] = il[j];

    float acc[27];
#pragma unroll
    for (int i = 0; i < 27; i++) acc[i] = 0.f;
#pragma unroll
    for (int j = 0; j < KNN; j++) {
        int m = il[j];
        float e[6];
        e[0] = sx[m] - qx; e[1] = sy[m] - qy; e[2] = sz[m] - qz;
        e[3] = qx; e[4] = qy; e[5] = qz;
        int t = 6;
#pragma unroll
        for (int a = 0; a < 6; a++) {
            acc[a] += e[a];
#pragma unroll
            for (int bb = a; bb < 6; bb++) acc[t++] += e[a] * e[bb];
        }
    }
#pragma unroll
    for (int i = 0; i < 27; i++) {
#pragma unroll
        for (int o = 16; o > 0; o >>= 1)
            acc[i] += __shfl_xor_sync(0xffffffffu, acc[i], o);
    }
    if ((tid & 31) == 0) {
#pragma unroll
        for (int i = 0; i < 27; i++) atomicAdd(&g_mom[i], acc[i]);
    }
}

__global__ void stats1_kernel(const float* __restrict__ W1,
                              const float* __restrict__ gamma1,
                              const float* __restrict__ beta1) {
    int c = threadIdx.x;
    if (c >= 64) return;
    float w[6];
#pragma unroll
    for (int j = 0; j < 6; j++) w[j] = W1[c * 6 + j];
    float m = 0.f;
#pragma unroll
    for (int j = 0; j < 6; j++) m += w[j] * g_mom[j];
    m /= NTOT;
    float qv = 0.f;
    int t = 6;
#pragma unroll
    for (int a = 0; a < 6; a++) {
#pragma unroll
        for (int bb = a; bb < 6; bb++) {
            float coef = (a == bb) ? 1.f : 2.f;
            qv += coef * w[a] * w[bb] * g_mom[t++];
        }
    }
    qv /= NTOT;
    float var = qv - m * m;
    float s = gamma1[c] * rsqrtf(var + EPSV);
    g_scale1[c] = s;
    g_shift1[c] = fmaf(-m, s, beta1[c]);
}

// ---------------- mma.sync main kernel ----------------
// SMEM byte offsets
#define S_BH   0                    // W2 hi bf16: 64 cols x 128B (k-contiguous)
#define S_BL   8192                 // W2 lo
#define S_RAW  16384                // 32 pts x 20 nbr x 16B raw coords
#define S_QUAD 26624                // 32 pts x 16B query coords
#define S_AD   28672                // A hi (20480) + A lo (20480) OR D (160 x 272)
#define S_TOT  (S_AD + 160*272)

#define SW(off) ((off) ^ (((off) >> 3) & 0x70))

__global__ __launch_bounds__(256, 2) void main_kernel(const float* __restrict__ x,
                                                      const float* __restrict__ W1,
                                                      const float* __restrict__ W2) {
    __shared__ __align__(1024) unsigned char S[S_TOT];
    __shared__ float schanS[64], schanQ[64];
    float* Sf = (float*)S;
    uint32_t sb = smem_u32(S);

    int tid = threadIdx.x;
    int lane = tid & 31;
    int w = tid >> 5;

    int pt0 = blockIdx.x * PTS;
    int b = pt0 >> 12;
    int n0 = pt0 & (NN - 1);
    int gbase = b * NN;
    const float* xb = x + b * 3 * NN;

    if (tid < 64) { schanS[tid] = 0.f; schanQ[tid] = 0.f; }

    // ---- stage W2 hi/lo (column c contiguous over j = k) ----
    for (int i = tid; i < 2048; i += 256) {
        int c = i >> 5, jp = i & 31;
        float v0 = W2[c * 64 + 2 * jp];
        float v1 = W2[c * 64 + 2 * jp + 1];
        uint32_t hp = bf2(v0, v1);
        float h0 = __uint_as_float(hp << 16);
        float h1 = __uint_as_float(hp & 0xffff0000u);
        uint32_t lp = bf2(v0 - h0, v1 - h1);
        *(uint32_t*)(S + S_BH + c * 128 + jp * 4) = hp;
        *(uint32_t*)(S + S_BL + c * 128 + jp * 4) = lp;
    }

    // ---- gather all 32 points' neighbor + query coords ----
    for (int u = tid; u < 672; u += 256) {
        if (u < 640) {
            int p = u / 20, k = u - p * 20;
            int nb = g_idx[(gbase + n0 + p) * KNN + k];
            float* d = &Sf[(S_RAW >> 2) + u * 4];
            d[0] = xb[nb]; d[1] = xb[NN + nb]; d[2] = xb[2 * NN + nb];
        } else {
            int p = u - 640;
            float* d = &Sf[(S_QUAD >> 2) + p * 4];
            d[0] = xb[n0 + p]; d[1] = xb[NN + n0 + p]; d[2] = xb[2 * NN + n0 + p];
        }
    }

    // ---- h1 weights for this thread's A-column pair (cols 2jp, 2jp+1) ----
    int jp = tid & 31;
    int p8 = tid >> 5;
    int cA = 2 * jp, cB = 2 * jp + 1;
    float wA[6], wB[6];
#pragma unroll
    for (int j = 0; j < 6; j++) { wA[j] = W1[cA * 6 + j]; wB[j] = W1[cB * 6 + j]; }
    wA[3] -= wA[0]; wA[4] -= wA[1]; wA[5] -= wA[2];
    wB[3] -= wB[0]; wB[4] -= wB[1]; wB[5] -= wB[2];
    float sA = g_scale1[cA], shA = g_shift1[cA];
    float sB = g_scale1[cB], shB = g_shift1[cB];

    __syncthreads();

    // ---- load B fragments (once; warp w owns n-tile w = channels 8w..8w+7) ----
    uint32_t bh[4][2], bl[4][2];
    {
        int col = w * 8 + (lane & 7);
        int khalf = (lane >> 3) & 1;
#pragma unroll
        for (int kt = 0; kt < 4; kt++) {
            uint32_t ba = sb + S_BH + col * 128 + kt * 32 + khalf * 16;
            asm volatile("ldmatrix.sync.aligned.m8n8.x2.shared.b16 {%0,%1}, [%2];"
                         : "=r"(bh[kt][0]), "=r"(bh[kt][1]) : "r"(ba));
            uint32_t bb2 = sb + S_BL + col * 128 + kt * 32 + khalf * 16;
            asm volatile("ldmatrix.sync.aligned.m8n8.x2.shared.b16 {%0,%1}, [%2];"
                         : "=r"(bl[kt][0]), "=r"(bl[kt][1]) : "r"(bb2));
        }
    }

    float sum0 = 0.f, ssq0 = 0.f, sum1 = 0.f, ssq1 = 0.f;
    int c2 = 2 * (tid & 31);

    for (int r = 0; r < 4; r++) {
        __syncthreads();   // AD region free (D consumed / first iter)

        // ---- h1 + BN1 + lrelu -> bf16 hi/lo A (row = p8*20+k, cols 2jp,2jp+1)
        int pl = r * 8 + p8;
        const float* qq = &Sf[(S_QUAD >> 2) + pl * 4];
        float qxx = qq[0], qyy = qq[1], qzz = qq[2];
#pragma unroll
        for (int k = 0; k < KNN; k++) {
            const float* e = &Sf[(S_RAW >> 2) + (pl * 20 + k) * 4];
            float ex = e[0], ey = e[1], ez = e[2];
            float h0 = ex * wA[0];
            h0 = fmaf(ey, wA[1], h0); h0 = fmaf(ez, wA[2], h0);
            h0 = fmaf(qxx, wA[3], h0); h0 = fmaf(qyy, wA[4], h0); h0 = fmaf(qzz, wA[5], h0);
            float h1v = ex * wB[0];
            h1v = fmaf(ey, wB[1], h1v); h1v = fmaf(ez, wB[2], h1v);
            h1v = fmaf(qxx, wB[3], h1v); h1v = fmaf(qyy, wB[4], h1v); h1v = fmaf(qzz, wB[5], h1v);
            float v0 = fmaf(sA, h0, shA);
            float v1 = fmaf(sB, h1v, shB);
            float g0 = fmaxf(v0, SLOPE * v0);
            float g1 = fmaxf(v1, SLOPE * v1);
            uint32_t hp = bf2(g0, g1);
            float hh0 = __uint_as_float(hp << 16);
            float hh1 = __uint_as_float(hp & 0xffff0000u);
            uint32_t lp = bf2(g0 - hh0, g1 - hh1);
            int row = p8 * 20 + k;
            uint32_t off = SW((uint32_t)(row * 128 + jp * 4));
            *(uint32_t*)(S + S_AD + off) = hp;
            *(uint32_t*)(S + S_AD + 20480 + off) = lp;
        }
        __syncthreads();

        // ---- MMA: warp w computes n-tile w over ALL 10 m-tiles (160 rows),
        //      K=64 (4 k-tiles), D = Ah*Bh + Al*Bh + Ah*Bl ----
        float D[10][4];
#pragma unroll
        for (int m = 0; m < 10; m++) {
            D[m][0] = 0.f; D[m][1] = 0.f; D[m][2] = 0.f; D[m][3] = 0.f;
        }
        int lrow = lane & 15;
        int kb2 = lane >> 4;
#pragma unroll
        for (int m = 0; m < 10; m++) {
#pragma unroll
            for (int kt = 0; kt < 4; kt++) {
                uint32_t aoff = SW((uint32_t)((m * 16 + lrow) * 128 + kt * 32 + kb2 * 16));
                uint32_t ah0, ah1, ah2, ah3, al0, al1, al2, al3;
                asm volatile("ldmatrix.sync.aligned.m8n8.x4.shared.b16 {%0,%1,%2,%3}, [%4];"
                             : "=r"(ah0), "=r"(ah1), "=r"(ah2), "=r"(ah3)
                             : "r"(sb + S_AD + aoff));
                asm volatile("ldmatrix.sync.aligned.m8n8.x4.shared.b16 {%0,%1,%2,%3}, [%4];"
                             : "=r"(al0), "=r"(al1), "=r"(al2), "=r"(al3)
                             : "r"(sb + S_AD + 20480 + aoff));
                asm volatile("mma.sync.aligned.m16n8k16.row.col.f32.bf16.bf16.f32 "
                             "{%0,%1,%2,%3}, {%4,%5,%6,%7}, {%8,%9}, {%0,%1,%2,%3};"
                             : "+f"(D[m][0]), "+f"(D[m][1]), "+f"(D[m][2]), "+f"(D[m][3])
                             : "r"(ah0), "r"(ah1), "r"(ah2), "r"(ah3),
                               "r"(bh[kt][0]), "r"(bh[kt][1]));
                asm volatile("mma.sync.aligned.m16n8k16.row.col.f32.bf16.bf16.f32 "
                             "{%0,%1,%2,%3}, {%4,%5,%6,%7}, {%8,%9}, {%0,%1,%2,%3};"
                             : "+f"(D[m][0]), "+f"(D[m][1]), "+f"(D[m][2]), "+f"(D[m][3])
                             : "r"(al0), "r"(al1), "r"(al2), "r"(al3),
                               "r"(bh[kt][0]), "r"(bh[kt][1]));
                asm volatile("mma.sync.aligned.m16n8k16.row.col.f32.bf16.bf16.f32 "
                             "{%0,%1,%2,%3}, {%4,%5,%6,%7}, {%8,%9}, {%0,%1,%2,%3};"
                             : "+f"(D[m][0]), "+f"(D[m][1]), "+f"(D[m][2]), "+f"(D[m][3])
                             : "r"(ah0), "r"(ah1), "r"(ah2), "r"(ah3),
                               "r"(bl[kt][0]), "r"(bl[kt][1]));
            }
        }
        __syncthreads();   // all warps done reading A; AD region becomes D

        // ---- D frags -> smem (row stride 272B spreads banks) ----
        {
            int col = w * 8 + 2 * (lane & 3);
#pragma unroll
            for (int m = 0; m < 10; m++) {
                int row0 = m * 16 + (lane >> 2);
                *(float2*)(S + S_AD + row0 * 272 + col * 4) = make_float2(D[m][0], D[m][1]);
                *(float2*)(S + S_AD + (row0 + 8) * 272 + col * 4) = make_float2(D[m][2], D[m][3]);
            }
        }
        __syncthreads();

        // ---- reduce over k: thread (p8, channels c2, c2+1) ----
        float mx0 = -CUDART_INF_F, mn0 = CUDART_INF_F;
        float mx1 = -CUDART_INF_F, mn1 = CUDART_INF_F;
#pragma unroll
        for (int k = 0; k < KNN; k++) {
            float2 v = *(const float2*)(S + S_AD + (p8 * 20 + k) * 272 + c2 * 4);
            mx0 = fmaxf(mx0, v.x); mn0 = fminf(mn0, v.x);
            mx1 = fmaxf(mx1, v.y); mn1 = fminf(mn1, v.y);
            sum0 += v.x; ssq0 = fmaf(v.x, v.x, ssq0);
            sum1 += v.y; ssq1 = fmaf(v.y, v.y, ssq1);
        }
        int gp = gbase + n0 + r * 8 + p8;
        *(float2*)&g_maxb[gp * 64 + c2] = make_float2(mx0, mx1);
        *(float2*)&g_minb[gp * 64 + c2] = make_float2(mn0, mn1);
    }

    __syncthreads();
    atomicAdd(&schanS[c2], sum0);
    atomicAdd(&schanQ[c2], ssq0);
    atomicAdd(&schanS[c2 + 1], sum1);
    atomicAdd(&schanQ[c2 + 1], ssq1);
    __syncthreads();
    if (tid < 64) {
        atomicAdd(&g_sum2[tid],   schanS[tid]);
        atomicAdd(&g_sumsq2[tid], schanQ[tid]);
    }
}

__global__ void stats2_kernel(const float* __restrict__ gamma2,
                              const float* __restrict__ beta2) {
    int c = threadIdx.x;
    if (c >= 64) return;
    float mean = g_sum2[c] / NTOT;
    float var = g_sumsq2[c] / NTOT - mean * mean;
    float s = gamma2[c] * rsqrtf(var + EPSV);
    g_scale2[c] = s;
    g_shift2[c] = fmaf(-mean, s, beta2[c]);
}

__global__ __launch_bounds__(256) void out_kernel(float* __restrict__ out) {
    __shared__ float tile[64][65];
    int b = blockIdx.y;
    int n0 = blockIdx.x * 64;
    int tid = threadIdx.x;
#pragma unroll
    for (int i = 0; i < 16; i++) {
        int flat = i * 256 + tid;
        int cc = flat & 63;
        int nl = flat >> 6;
        float s = g_scale2[cc];
        int gi = (b * NN + n0 + nl) * 64 + cc;
        float v;
        if (s >= 0.f) v = g_maxb[gi]; else v = g_minb[gi];
        float u = fmaf(s, v, g_shift2[cc]);
        tile[nl][cc] = fmaxf(u, SLOPE * u);
    }
    __syncthreads();
#pragma unroll
    for (int i = 0; i < 16; i++) {
        int flat = i * 256 + tid;
        int nl = flat & 63;
        int cc = flat >> 6;
        out[(b * 64 + cc) * NN + n0 + nl] = tile[nl][cc];
    }
}

extern "C" void kernel_launch(void* const* d_in, const int* in_sizes, int n_in,
                              void* d_out, int out_size) {
    const float* x      = (const float*)d_in[0];
    const float* W1     = (const float*)d_in[1];
    const float* gamma1 = (const float*)d_in[2];
    const float* beta1  = (const float*)d_in[3];
    const float* W2     = (const float*)d_in[4];
    const float* gamma2 = (const float*)d_in[5];
    const float* beta2  = (const float*)d_in[6];
    float* out = (float*)d_out;

    zero_kernel<<<1, 64>>>();
    knn_kernel<<<dim3(NN / 128, BB), 128>>>(x);
    stats1_kernel<<<1, 64>>>(W1, gamma1, beta1);
    main_kernel<<<BB * NN / PTS, 256>>>(x, W1, W2);
    stats2_kernel<<<1, 64>>>(gamma2, beta2);
    out_kernel<<<dim3(NN / 64, BB), 256>>>(out);
}